// round 1
// baseline (speedup 1.0000x reference)
#include <cuda_runtime.h>
#include <math.h>

#define Bn 16
#define Tn 1024
#define Dn 512
#define Hn 8
#define HDn 64
#define COUTn 7
#define PREDn 96
#define Kn 8
#define LATENTn 2048
#define TP (Tn + PREDn)   /* 1120 */
#define T1 (Tn + 1)       /* 1025 */

// Output packing (floats): res3, level_out, growth, season
#define OFF_RES3   0
#define OFF_LEVEL  (Bn*Tn*Dn)                       /* 8388608 */
#define OFF_GROWTH (OFF_LEVEL + Bn*Tn*COUTn)        /* 8503296 */
#define OFF_SEASON (OFF_GROWTH + Bn*T1*Dn)          /* 16900096 */

// ---------------- scratch (static device arrays; no allocation) ----------------
__device__ float RES1[Bn*Tn*Dn];
__device__ float VBUF[Bn*Tn*Dn];
__device__ float GBUF[Bn*T1*Dn];
__device__ float R2B [Bn*Tn*Dn];
__device__ float FBUF[Bn*Tn*LATENTn];
__device__ float FOUT[Bn*Tn*Dn];
__device__ float TK_RE[Bn*Kn*Dn];
__device__ float TK_IM[Bn*Kn*Dn];
__device__ int   TK_M [Bn*Kn*Dn];
__device__ float GS_G[Bn*Tn*COUTn];
__device__ float GS_S[Bn*Tn*COUTn];

// ---------------- FFT (radix-2 DIF, 1024-pt) + top-8 per series ----------------
__global__ __launch_bounds__(256) void fft_topk_kernel(const float* __restrict__ x) {
    __shared__ float2 data[4][1024];   // 32 KB
    __shared__ float2 tw[512];         // 4 KB
    int tid = threadIdx.x;
    int b   = blockIdx.x >> 7;         // 128 groups of 4 d's per batch
    int d0  = (blockIdx.x & 127) << 2;

    for (int k = tid; k < 512; k += 256) {
        float s, c;
        sincosf(-6.283185307179586f * (float)k / 1024.0f, &s, &c);
        tw[k] = make_float2(c, s);     // e^{-i 2pi k/1024}
    }
    const float* xb = x + (size_t)b * Tn * Dn;
    for (int i = tid; i < 4096; i += 256) {
        int t = i >> 2, j = i & 3;
        data[j][t] = make_float2(xb[(size_t)t*Dn + d0 + j], 0.f);
    }
    __syncthreads();

    int tmul = 1;
    for (int half = 512; half >= 1; half >>= 1, tmul <<= 1) {
        for (int i = tid; i < 2048; i += 256) {
            int s  = i >> 9;
            int bf = i & 511;
            int k  = bf & (half - 1);
            int pos = 2*bf - k;            // blk*len + k
            float2 u = data[s][pos], v = data[s][pos + half];
            data[s][pos] = make_float2(u.x + v.x, u.y + v.y);
            float2 t2 = make_float2(u.x - v.x, u.y - v.y);
            float2 w  = tw[k * tmul];
            data[s][pos + half] = make_float2(t2.x*w.x - t2.y*w.y,
                                              t2.x*w.y + t2.y*w.x);
        }
        __syncthreads();
    }
    // output is bit-reversed: X[f] lives at data[s][brev10(f)]

    int wid = tid >> 5, lane = tid & 31;
    if (wid < 4) {
        int s = wid;
        int chosen[8];
#pragma unroll
        for (int q = 0; q < 8; q++) chosen[q] = -1;
#pragma unroll
        for (int it = 0; it < 8; it++) {
            float bestm = -1.f; int bestf = 1 << 20;
            for (int f = 1 + lane; f <= 511; f += 32) {
                bool used = false;
#pragma unroll
                for (int q = 0; q < 8; q++) used |= (chosen[q] == f);
                if (used) continue;
                int j = (int)(__brev((unsigned)f) >> 22);
                float2 v = data[s][j];
                float m2 = v.x*v.x + v.y*v.y;
                if (m2 > bestm || (m2 == bestm && f < bestf)) { bestm = m2; bestf = f; }
            }
            for (int off = 16; off; off >>= 1) {
                float om = __shfl_xor_sync(0xffffffffu, bestm, off);
                int   of = __shfl_xor_sync(0xffffffffu, bestf, off);
                if (om > bestm || (om == bestm && of < bestf)) { bestm = om; bestf = of; }
            }
            chosen[it] = bestf;
        }
        if (lane == 0) {
            int d = d0 + s;
#pragma unroll
            for (int it = 0; it < 8; it++) {
                int f = chosen[it];
                int j = (int)(__brev((unsigned)f) >> 22);
                float2 v = data[s][j];
                size_t o = ((size_t)b * Kn + it) * Dn + d;
                TK_M[o] = f; TK_RE[o] = v.x; TK_IM[o] = v.y;
            }
        }
    }
}

// ---------------- season reconstruction + res1 ----------------
__global__ __launch_bounds__(256) void season_kernel(const float* __restrict__ res,
                                                     float* __restrict__ out) {
    __shared__ float ctab[1024];
    for (int j = threadIdx.x; j < 1024; j += 256)
        ctab[j] = cosf(6.283185307179586f / 1024.0f * (float)j);
    __syncthreads();

    int d  = blockIdx.x * 256 + threadIdx.x;  // 0..511
    int b  = blockIdx.y;
    int t0 = blockIdx.z * 112;                // 10 chunks * 112 = 1120

    int ms[8]; float re[8], im[8];
#pragma unroll
    for (int k = 0; k < 8; k++) {
        size_t o = ((size_t)b*Kn + k)*Dn + d;
        ms[k] = TK_M[o];
        re[k] = TK_RE[o] * (2.0f / (float)Tn);
        im[k] = TK_IM[o] * (2.0f / (float)Tn);
    }
    float*       seas = out + OFF_SEASON + (size_t)b*TP*Dn;
    const float* rb   = res + (size_t)b*Tn*Dn;
    float*       r1   = RES1 + (size_t)b*Tn*Dn;

    for (int t = t0; t < t0 + 112; t++) {
        float acc = 0.f;
#pragma unroll
        for (int k = 0; k < 8; k++) {
            int idx = (ms[k]*t) & 1023;
            acc += re[k]*ctab[idx] - im[k]*ctab[(idx + 768) & 1023];
        }
        seas[(size_t)t*Dn + d] = acc;
        if (t < Tn) r1[(size_t)t*Dn + d] = rb[(size_t)t*Dn + d] - acc;
    }
}

// ---------------- SGEMM 128x128x8, 256 threads, 8x8 micro ----------------
__global__ __launch_bounds__(256) void sgemm_kernel(const float* __restrict__ A,
                                                    const float* __restrict__ Bm,
                                                    float* __restrict__ C,
                                                    int M, int N, int K, int dogelu) {
    __shared__ float As[8][128];
    __shared__ float Bs[8][128];
    int tid = threadIdx.x;
    int row0 = blockIdx.y * 128, col0 = blockIdx.x * 128;
    int arow = tid >> 1, acol4 = (tid & 1) * 4;
    int brow = tid >> 5, bcol4 = (tid & 31) * 4;
    int ty = tid >> 4, tx = tid & 15;
    float acc[8][8] = {};

    for (int k0 = 0; k0 < K; k0 += 8) {
        float4 av = make_float4(0.f, 0.f, 0.f, 0.f);
        int gr = row0 + arow;
        if (gr < M) av = *(const float4*)(A + (size_t)gr*K + k0 + acol4);
        As[acol4+0][arow] = av.x; As[acol4+1][arow] = av.y;
        As[acol4+2][arow] = av.z; As[acol4+3][arow] = av.w;
        *(float4*)(&Bs[brow][bcol4]) =
            *(const float4*)(Bm + (size_t)(k0 + brow)*N + col0 + bcol4);
        __syncthreads();
#pragma unroll
        for (int kk = 0; kk < 8; kk++) {
            float af[8], bf[8];
            *(float4*)(af)   = *(const float4*)(&As[kk][ty*8]);
            *(float4*)(af+4) = *(const float4*)(&As[kk][ty*8+4]);
            *(float4*)(bf)   = *(const float4*)(&Bs[kk][tx*8]);
            *(float4*)(bf+4) = *(const float4*)(&Bs[kk][tx*8+4]);
#pragma unroll
            for (int i = 0; i < 8; i++)
#pragma unroll
                for (int j = 0; j < 8; j++)
                    acc[i][j] += af[i]*bf[j];
        }
        __syncthreads();
    }
#pragma unroll
    for (int i = 0; i < 8; i++) {
        int gr = row0 + ty*8 + i;
        if (gr >= M) break;
        float* cp = C + (size_t)gr*N + col0 + tx*8;
        float v[8];
#pragma unroll
        for (int j = 0; j < 8; j++) {
            float u = acc[i][j];
            if (dogelu) u = 0.5f*u*(1.0f + erff(u*0.70710678118654752f));
            v[j] = u;
        }
        *(float4*)(cp)   = *(const float4*)(v);
        *(float4*)(cp+4) = *(const float4*)(v+4);
    }
}

// ---------------- growth: first differences + EMA ----------------
__global__ __launch_bounds__(256) void growth_smooth_kernel(const float* __restrict__ sw,
                                                            const float* __restrict__ z0,
                                                            const float* __restrict__ v0) {
    int gid = blockIdx.x*256 + threadIdx.x;  // 0..8191
    int b = gid >> 9, c = gid & 511;
    int h = c >> 6;
    float w   = 1.f/(1.f + expf(-sw[h]));
    float omw = 1.f - w;
    float y    = v0[c];
    float prev = z0[c];
    const float* vp = VBUF + (size_t)b*Tn*Dn + c;
    float*       gp = GBUF + (size_t)b*T1*Dn + c;
    gp[0] = y;
    for (int t = 0; t < Tn; t++) {
        float vt = vp[(size_t)t*Dn];
        float dv = vt - prev; prev = vt;
        y = w*y + omw*dv;
        gp[(size_t)(t+1)*Dn] = y;
    }
}

// ---------------- layernorm helpers ----------------
__device__ __forceinline__ float block_reduce_sum(float v, float* red) {
    for (int o = 16; o; o >>= 1) v += __shfl_xor_sync(0xffffffffu, v, o);
    int wid = threadIdx.x >> 5;
    if ((threadIdx.x & 31) == 0) red[wid] = v;
    __syncthreads();
    if (threadIdx.x < 32) {
        float s = (threadIdx.x < 4) ? red[threadIdx.x] : 0.f;
        for (int o = 2; o; o >>= 1) s += __shfl_xor_sync(0xffffffffu, s, o);
        if (threadIdx.x == 0) red[0] = s;
    }
    __syncthreads();
    float r = red[0];
    __syncthreads();
    return r;
}

// res2 = LN(res1 - growth[:,1:])
__global__ __launch_bounds__(128) void res2_kernel(const float* __restrict__ out_all,
                                                   const float* __restrict__ ng,
                                                   const float* __restrict__ nb) {
    __shared__ float red[32];
    int r = blockIdx.x;               // b*Tn + t
    int b = r >> 10, t = r & 1023;
    const float* x1 = RES1 + (size_t)r*Dn;
    const float* gw = out_all + OFF_GROWTH + (size_t)(b*T1 + t + 1)*Dn;
    float vals[4]; float s = 0.f;
#pragma unroll
    for (int i = 0; i < 4; i++) {
        int d = threadIdx.x + i*128;
        vals[i] = x1[d] - gw[d];
        s += vals[i];
    }
    float mu = block_reduce_sum(s, red) * (1.0f/512.0f);
    float vs = 0.f;
#pragma unroll
    for (int i = 0; i < 4; i++) { float c = vals[i]-mu; vs += c*c; }
    float var = block_reduce_sum(vs, red) * (1.0f/512.0f);
    float inv = rsqrtf(var + 1e-5f);
#pragma unroll
    for (int i = 0; i < 4; i++) {
        int d = threadIdx.x + i*128;
        R2B[(size_t)r*Dn + d] = (vals[i]-mu)*inv*ng[d] + nb[d];
    }
}

// res3 = LN(res2 + ffn) -> d_out
__global__ __launch_bounds__(128) void res3_kernel(float* __restrict__ out_all,
                                                   const float* __restrict__ ng,
                                                   const float* __restrict__ nb) {
    __shared__ float red[32];
    int r = blockIdx.x;
    float vals[4]; float s = 0.f;
#pragma unroll
    for (int i = 0; i < 4; i++) {
        int d = threadIdx.x + i*128;
        vals[i] = R2B[(size_t)r*Dn + d] + FOUT[(size_t)r*Dn + d];
        s += vals[i];
    }
    float mu = block_reduce_sum(s, red) * (1.0f/512.0f);
    float vs = 0.f;
#pragma unroll
    for (int i = 0; i < 4; i++) { float c = vals[i]-mu; vs += c*c; }
    float var = block_reduce_sum(vs, red) * (1.0f/512.0f);
    float inv = rsqrtf(var + 1e-5f);
#pragma unroll
    for (int i = 0; i < 4; i++) {
        int d = threadIdx.x + i*128;
        out_all[OFF_RES3 + (size_t)r*Dn + d] = (vals[i]-mu)*inv*ng[d] + nb[d];
    }
}

// ---------------- level projections (growth@gpw, season@spw) ----------------
__global__ __launch_bounds__(256) void levelproj_kernel(const float* __restrict__ out_all,
                                                        const float* __restrict__ gpw,
                                                        const float* __restrict__ spw) {
    int warp = (blockIdx.x*256 + threadIdx.x) >> 5;
    int lane = threadIdx.x & 31;
    if (warp >= Bn*Tn) return;
    int b = warp >> 10, t = warp & 1023;
    const float* gr = out_all + OFF_GROWTH + (size_t)(b*T1 + t)*Dn;
    const float* se = out_all + OFF_SEASON + (size_t)(b*TP + t)*Dn;
    float ag[7] = {}, as_[7] = {};
    for (int d = lane; d < 512; d += 32) {
        float g = gr[d], s = se[d];
#pragma unroll
        for (int c = 0; c < 7; c++) { ag[c] += g*gpw[d*7+c]; as_[c] += s*spw[d*7+c]; }
    }
#pragma unroll
    for (int c = 0; c < 7; c++) {
        for (int o = 16; o; o >>= 1) {
            ag[c]  += __shfl_xor_sync(0xffffffffu, ag[c],  o);
            as_[c] += __shfl_xor_sync(0xffffffffu, as_[c], o);
        }
    }
    if (lane == 0) {
#pragma unroll
        for (int c = 0; c < 7; c++) {
            GS_G[(size_t)warp*7 + c] = ag[c];
            GS_S[(size_t)warp*7 + c] = as_[c];
        }
    }
}

// ---------------- level EMA with aux ----------------
__global__ void level_kernel(const float* __restrict__ level,
                             const float* __restrict__ lsw,
                             const float* __restrict__ lv0,
                             float* __restrict__ out_all) {
    int gid = threadIdx.x;
    if (gid >= Bn*COUTn) return;
    int b = gid / COUTn, c = gid % COUTn;
    float w   = 1.f/(1.f + expf(-lsw[c]));
    float omw = 1.f - w;
    float y = lv0[c];
    const float* lp = level + (size_t)b*Tn*COUTn + c;
    const float* gp = GS_G  + (size_t)b*Tn*COUTn + c;
    const float* sp = GS_S  + (size_t)b*Tn*COUTn + c;
    float* op = out_all + OFF_LEVEL + (size_t)b*Tn*COUTn + c;
    for (int t = 0; t < Tn; t++) {
        float val = lp[t*COUTn] - sp[t*COUTn];
        y = w*y + omw*val + w*gp[t*COUTn];
        op[t*COUTn] = y;
    }
}

// ---------------- launch ----------------
extern "C" void kernel_launch(void* const* d_in, const int* in_sizes, int n_in,
                              void* d_out, int out_size) {
    const float* res      = (const float*)d_in[0];
    const float* level    = (const float*)d_in[1];
    const float* in_w     = (const float*)d_in[2];
    const float* out_w    = (const float*)d_in[3];
    const float* z0       = (const float*)d_in[4];
    const float* gsw      = (const float*)d_in[5];
    const float* gv0      = (const float*)d_in[6];
    const float* ff_w1    = (const float*)d_in[7];
    const float* ff_w2    = (const float*)d_in[8];
    const float* n1g      = (const float*)d_in[9];
    const float* n1b      = (const float*)d_in[10];
    const float* n2g      = (const float*)d_in[11];
    const float* n2b      = (const float*)d_in[12];
    const float* gpw      = (const float*)d_in[13];
    const float* spw      = (const float*)d_in[14];
    const float* lsw      = (const float*)d_in[15];
    const float* lv0      = (const float*)d_in[16];
    float* out = (float*)d_out;

    float *pRES1, *pVBUF, *pGBUF, *pR2, *pFBUF, *pFOUT;
    cudaGetSymbolAddress((void**)&pRES1, RES1);
    cudaGetSymbolAddress((void**)&pVBUF, VBUF);
    cudaGetSymbolAddress((void**)&pGBUF, GBUF);
    cudaGetSymbolAddress((void**)&pR2,   R2B);
    cudaGetSymbolAddress((void**)&pFBUF, FBUF);
    cudaGetSymbolAddress((void**)&pFOUT, FOUT);

    // 1) FFT + top-k
    fft_topk_kernel<<<Bn*(Dn/4), 256>>>(res);
    // 2) season + res1
    season_kernel<<<dim3(2, Bn, 10), 256>>>(res, out);
    // 3) v = res1 @ in_proj_w
    sgemm_kernel<<<dim3(Dn/128, (Bn*Tn)/128), 256>>>(pRES1, in_w, pVBUF,
                                                     Bn*Tn, Dn, Dn, 0);
    // 4) diffs + EMA -> GBUF [B,T+1,512]
    growth_smooth_kernel<<<Bn*Dn/256, 256>>>(gsw, z0, gv0);
    // 5) growth = GBUF @ out_proj_w  -> d_out
    sgemm_kernel<<<dim3(Dn/128, (Bn*T1 + 127)/128), 256>>>(pGBUF, out_w,
                                                           out + OFF_GROWTH,
                                                           Bn*T1, Dn, Dn, 0);
    // 6) res2 = LN(res1 - growth[:,1:])
    res2_kernel<<<Bn*Tn, 128>>>(out, n1g, n1b);
    // 7) ffn1 = gelu(res2 @ ff_w1)
    sgemm_kernel<<<dim3(LATENTn/128, (Bn*Tn)/128), 256>>>(pR2, ff_w1, pFBUF,
                                                          Bn*Tn, LATENTn, Dn, 1);
    // 8) ffn2 = ffn1 @ ff_w2
    sgemm_kernel<<<dim3(Dn/128, (Bn*Tn)/128), 256>>>(pFBUF, ff_w2, pFOUT,
                                                     Bn*Tn, Dn, LATENTn, 0);
    // 9) res3 = LN(res2 + ffn2) -> d_out
    res3_kernel<<<Bn*Tn, 128>>>(out, n2g, n2b);
    // 10) g = growth[:, :T] @ gpred_w ; s = season[:, :T] @ spred_w
    levelproj_kernel<<<(Bn*Tn*32)/256, 256>>>(out, gpw, spw);
    // 11) level EMA with aux -> d_out
    level_kernel<<<1, 128>>>(level, lsw, lv0, out);
}

// round 2
// speedup vs baseline: 2.2597x; 2.2597x over previous
#include <cuda_runtime.h>
#include <math.h>

#define Bn 16
#define Tn 1024
#define Dn 512
#define Hn 8
#define HDn 64
#define COUTn 7
#define PREDn 96
#define Kn 8
#define LATENTn 2048
#define TP (Tn + PREDn)   /* 1120 */
#define T1 (Tn + 1)       /* 1025 */

#define OFF_RES3   0
#define OFF_LEVEL  (Bn*Tn*Dn)
#define OFF_GROWTH (OFF_LEVEL + Bn*Tn*COUTn)
#define OFF_SEASON (OFF_GROWTH + Bn*T1*Dn)

#define GSEG 16
#define GSEGLEN 64

// ---------------- scratch ----------------
__device__ float RES1[Bn*Tn*Dn];
__device__ float VBUF[Bn*Tn*Dn];
__device__ float GBUF[Bn*T1*Dn];
__device__ float R2B [Bn*Tn*Dn];
__device__ float FBUF[Bn*Tn*LATENTn];
__device__ float FOUT[Bn*Tn*Dn];
__device__ float TK_RE[Bn*Kn*Dn];
__device__ float TK_IM[Bn*Kn*Dn];
__device__ int   TK_M [Bn*Kn*Dn];
__device__ float GS_G[Bn*Tn*COUTn];
__device__ float GS_S[Bn*Tn*COUTn];
__device__ float GZ    [Bn*Dn*GSEG];
__device__ float GCARRY[Bn*Dn*GSEG];
__device__ float LZ    [Bn*COUTn*GSEG];
__device__ float LCARRY[Bn*COUTn*GSEG];

// ---------------- FFT (radix-2 DIF, 1024-pt) + top-8 per series ----------------
__global__ __launch_bounds__(256) void fft_topk_kernel(const float* __restrict__ x) {
    __shared__ float2 data[4][1024];
    __shared__ float2 tw[512];
    int tid = threadIdx.x;
    int b   = blockIdx.x >> 7;
    int d0  = (blockIdx.x & 127) << 2;

    for (int k = tid; k < 512; k += 256) {
        float s, c;
        sincosf(-6.283185307179586f * (float)k / 1024.0f, &s, &c);
        tw[k] = make_float2(c, s);
    }
    const float* xb = x + (size_t)b * Tn * Dn;
    for (int i = tid; i < 4096; i += 256) {
        int t = i >> 2, j = i & 3;
        data[j][t] = make_float2(xb[(size_t)t*Dn + d0 + j], 0.f);
    }
    __syncthreads();

    int tmul = 1;
    for (int half = 512; half >= 1; half >>= 1, tmul <<= 1) {
        for (int i = tid; i < 2048; i += 256) {
            int s  = i >> 9;
            int bf = i & 511;
            int k  = bf & (half - 1);
            int pos = 2*bf - k;
            float2 u = data[s][pos], v = data[s][pos + half];
            data[s][pos] = make_float2(u.x + v.x, u.y + v.y);
            float2 t2 = make_float2(u.x - v.x, u.y - v.y);
            float2 w  = tw[k * tmul];
            data[s][pos + half] = make_float2(t2.x*w.x - t2.y*w.y,
                                              t2.x*w.y + t2.y*w.x);
        }
        __syncthreads();
    }

    int wid = tid >> 5, lane = tid & 31;
    if (wid < 4) {
        int s = wid;
        int chosen[8];
#pragma unroll
        for (int q = 0; q < 8; q++) chosen[q] = -1;
#pragma unroll
        for (int it = 0; it < 8; it++) {
            float bestm = -1.f; int bestf = 1 << 20;
            for (int f = 1 + lane; f <= 511; f += 32) {
                bool used = false;
#pragma unroll
                for (int q = 0; q < 8; q++) used |= (chosen[q] == f);
                if (used) continue;
                int j = (int)(__brev((unsigned)f) >> 22);
                float2 v = data[s][j];
                float m2 = v.x*v.x + v.y*v.y;
                if (m2 > bestm || (m2 == bestm && f < bestf)) { bestm = m2; bestf = f; }
            }
            for (int off = 16; off; off >>= 1) {
                float om = __shfl_xor_sync(0xffffffffu, bestm, off);
                int   of = __shfl_xor_sync(0xffffffffu, bestf, off);
                if (om > bestm || (om == bestm && of < bestf)) { bestm = om; bestf = of; }
            }
            chosen[it] = bestf;
        }
        if (lane == 0) {
            int d = d0 + s;
#pragma unroll
            for (int it = 0; it < 8; it++) {
                int f = chosen[it];
                int j = (int)(__brev((unsigned)f) >> 22);
                float2 v = data[s][j];
                size_t o = ((size_t)b * Kn + it) * Dn + d;
                TK_M[o] = f; TK_RE[o] = v.x; TK_IM[o] = v.y;
            }
        }
    }
}

// ---------------- season reconstruction + res1 ----------------
__global__ __launch_bounds__(256) void season_kernel(const float* __restrict__ res,
                                                     float* __restrict__ out) {
    __shared__ float ctab[1024];
    for (int j = threadIdx.x; j < 1024; j += 256)
        ctab[j] = cosf(6.283185307179586f / 1024.0f * (float)j);
    __syncthreads();

    int d  = blockIdx.x * 256 + threadIdx.x;
    int b  = blockIdx.y;
    int t0 = blockIdx.z * 112;

    int ms[8]; float re[8], im[8];
#pragma unroll
    for (int k = 0; k < 8; k++) {
        size_t o = ((size_t)b*Kn + k)*Dn + d;
        ms[k] = TK_M[o];
        re[k] = TK_RE[o] * (2.0f / (float)Tn);
        im[k] = TK_IM[o] * (2.0f / (float)Tn);
    }
    float*       seas = out + OFF_SEASON + (size_t)b*TP*Dn;
    const float* rb   = res + (size_t)b*Tn*Dn;
    float*       r1   = RES1 + (size_t)b*Tn*Dn;

    for (int t = t0; t < t0 + 112; t++) {
        float acc = 0.f;
#pragma unroll
        for (int k = 0; k < 8; k++) {
            int idx = (ms[k]*t) & 1023;
            acc += re[k]*ctab[idx] - im[k]*ctab[(idx + 768) & 1023];
        }
        seas[(size_t)t*Dn + d] = acc;
        if (t < Tn) r1[(size_t)t*Dn + d] = rb[(size_t)t*Dn + d] - acc;
    }
}

// ---------------- TF32 tensor-core GEMM: 128x128 block, 64x32 warp ----------------
__device__ __forceinline__ unsigned f2tf32(float f) {
    unsigned u;
    asm("cvt.rna.tf32.f32 %0, %1;" : "=r"(u) : "f"(f));
    return u;
}

__global__ __launch_bounds__(256) void tf32gemm_kernel(const float* __restrict__ A,
                                                       const float* __restrict__ Bm,
                                                       float* __restrict__ C,
                                                       int M, int N, int K, int dogelu) {
    __shared__ unsigned As[16][136];
    __shared__ unsigned Bs[16][136];
    int tid = threadIdx.x;
    int row0 = blockIdx.y * 128, col0 = blockIdx.x * 128;
    int wid = tid >> 5, lane = tid & 31;
    int wm = (wid & 1) * 64, wn = (wid >> 1) * 32;
    int g = lane >> 2, tg = lane & 3;
    int arow = tid >> 1, akq = (tid & 1) * 8;
    int bkrow = tid >> 4, bnq = (tid & 15) * 8;

    float acc[4][4][4];
#pragma unroll
    for (int i = 0; i < 4; i++)
#pragma unroll
        for (int j = 0; j < 4; j++)
#pragma unroll
            for (int q = 0; q < 4; q++) acc[i][j][q] = 0.f;

    for (int k0 = 0; k0 < K; k0 += 16) {
        float4 a0v = make_float4(0.f,0.f,0.f,0.f), a1v = a0v;
        int gr = row0 + arow;
        if (gr < M) {
            const float* ap = A + (size_t)gr*K + k0 + akq;
            a0v = *(const float4*)(ap);
            a1v = *(const float4*)(ap + 4);
        }
        As[akq+0][arow] = f2tf32(a0v.x);
        As[akq+1][arow] = f2tf32(a0v.y);
        As[akq+2][arow] = f2tf32(a0v.z);
        As[akq+3][arow] = f2tf32(a0v.w);
        As[akq+4][arow] = f2tf32(a1v.x);
        As[akq+5][arow] = f2tf32(a1v.y);
        As[akq+6][arow] = f2tf32(a1v.z);
        As[akq+7][arow] = f2tf32(a1v.w);

        const float* bp = Bm + (size_t)(k0 + bkrow)*N + col0 + bnq;
        float4 b0v = *(const float4*)(bp);
        float4 b1v = *(const float4*)(bp + 4);
        unsigned* bs = &Bs[bkrow][bnq];
        bs[0] = f2tf32(b0v.x); bs[1] = f2tf32(b0v.y);
        bs[2] = f2tf32(b0v.z); bs[3] = f2tf32(b0v.w);
        bs[4] = f2tf32(b1v.x); bs[5] = f2tf32(b1v.y);
        bs[6] = f2tf32(b1v.z); bs[7] = f2tf32(b1v.w);
        __syncthreads();

#pragma unroll
        for (int kk = 0; kk < 16; kk += 8) {
            unsigned af[4][4], bf[4][2];
#pragma unroll
            for (int mt = 0; mt < 4; mt++) {
                int m = wm + mt*16 + g;
                af[mt][0] = As[kk+tg  ][m];
                af[mt][1] = As[kk+tg  ][m+8];
                af[mt][2] = As[kk+tg+4][m];
                af[mt][3] = As[kk+tg+4][m+8];
            }
#pragma unroll
            for (int nt = 0; nt < 4; nt++) {
                int n = wn + nt*8 + g;
                bf[nt][0] = Bs[kk+tg  ][n];
                bf[nt][1] = Bs[kk+tg+4][n];
            }
#pragma unroll
            for (int mt = 0; mt < 4; mt++)
#pragma unroll
                for (int nt = 0; nt < 4; nt++)
                    asm volatile(
                        "mma.sync.aligned.m16n8k8.row.col.f32.tf32.tf32.f32 "
                        "{%0,%1,%2,%3}, {%4,%5,%6,%7}, {%8,%9}, {%0,%1,%2,%3};"
                        : "+f"(acc[mt][nt][0]), "+f"(acc[mt][nt][1]),
                          "+f"(acc[mt][nt][2]), "+f"(acc[mt][nt][3])
                        : "r"(af[mt][0]), "r"(af[mt][1]), "r"(af[mt][2]), "r"(af[mt][3]),
                          "r"(bf[nt][0]), "r"(bf[nt][1]));
        }
        __syncthreads();
    }

#pragma unroll
    for (int mt = 0; mt < 4; mt++) {
#pragma unroll
        for (int nt = 0; nt < 4; nt++) {
            int r0 = row0 + wm + mt*16 + g;
            int c  = col0 + wn + nt*8 + 2*tg;
            float v[4];
#pragma unroll
            for (int q = 0; q < 4; q++) {
                float u = acc[mt][nt][q];
                if (dogelu) u = 0.5f*u*(1.0f + erff(u*0.70710678118654752f));
                v[q] = u;
            }
            if (r0 < M)     *(float2*)(C + (size_t)r0*N + c)     = make_float2(v[0], v[1]);
            if (r0 + 8 < M) *(float2*)(C + (size_t)(r0+8)*N + c) = make_float2(v[2], v[3]);
        }
    }
}

// ---------------- growth EMA: blocked parallel scan ----------------
__global__ __launch_bounds__(256) void growth_passA(const float* __restrict__ sw,
                                                    const float* __restrict__ z0) {
    int gid = blockIdx.x*256 + threadIdx.x;      // 131072
    int c = gid & 511;
    int r = gid >> 9;
    int b = r & 15, seg = r >> 4;
    float w = 1.f/(1.f + expf(-sw[c >> 6]));
    int t0 = seg * GSEGLEN;
    const float* vp = VBUF + (size_t)b*Tn*Dn + c;
    float prev = (t0 == 0) ? z0[c] : vp[(size_t)(t0-1)*Dn];
    float z = 0.f;
#pragma unroll 4
    for (int l = 0; l < GSEGLEN; l++) {
        float v = vp[(size_t)(t0+l)*Dn];
        z = w*z + (v - prev);
        prev = v;
    }
    GZ[(size_t)((b<<9)+c)*GSEG + seg] = z;
}

__global__ __launch_bounds__(256) void growth_carry(const float* __restrict__ sw,
                                                    const float* __restrict__ v0) {
    int ch = blockIdx.x*256 + threadIdx.x;       // 8192
    int c = ch & 511;
    float w = 1.f/(1.f + expf(-sw[c >> 6]));
    float w64 = 1.f;
    { float p = w; int e = GSEGLEN; while (e) { if (e & 1) w64 *= p; p *= p; e >>= 1; } }
    float y = v0[c];
    float omw = 1.f - w;
#pragma unroll
    for (int seg = 0; seg < GSEG; seg++) {
        GCARRY[(size_t)ch*GSEG + seg] = y;
        y = w64*y + omw*GZ[(size_t)ch*GSEG + seg];
    }
}

__global__ __launch_bounds__(256) void growth_passB(const float* __restrict__ sw,
                                                    const float* __restrict__ z0,
                                                    const float* __restrict__ v0) {
    int gid = blockIdx.x*256 + threadIdx.x;
    int c = gid & 511;
    int r = gid >> 9;
    int b = r & 15, seg = r >> 4;
    float w = 1.f/(1.f + expf(-sw[c >> 6]));
    float omw = 1.f - w;
    int t0 = seg * GSEGLEN;
    const float* vp = VBUF + (size_t)b*Tn*Dn + c;
    float*       gp = GBUF + (size_t)b*T1*Dn + c;
    float prev = (t0 == 0) ? z0[c] : vp[(size_t)(t0-1)*Dn];
    float y = GCARRY[(size_t)((b<<9)+c)*GSEG + seg];
    if (seg == 0) gp[0] = v0[c];
#pragma unroll 4
    for (int l = 0; l < GSEGLEN; l++) {
        float v = vp[(size_t)(t0+l)*Dn];
        y = w*y + omw*(v - prev);
        prev = v;
        gp[(size_t)(t0+l+1)*Dn] = y;
    }
}

// ---------------- layernorm helpers ----------------
__device__ __forceinline__ float block_reduce_sum(float v, float* red) {
    for (int o = 16; o; o >>= 1) v += __shfl_xor_sync(0xffffffffu, v, o);
    int wid = threadIdx.x >> 5;
    if ((threadIdx.x & 31) == 0) red[wid] = v;
    __syncthreads();
    if (threadIdx.x < 32) {
        float s = (threadIdx.x < 4) ? red[threadIdx.x] : 0.f;
        for (int o = 2; o; o >>= 1) s += __shfl_xor_sync(0xffffffffu, s, o);
        if (threadIdx.x == 0) red[0] = s;
    }
    __syncthreads();
    float r = red[0];
    __syncthreads();
    return r;
}

__global__ __launch_bounds__(128) void res2_kernel(const float* __restrict__ out_all,
                                                   const float* __restrict__ ng,
                                                   const float* __restrict__ nb) {
    __shared__ float red[32];
    int r = blockIdx.x;
    int b = r >> 10, t = r & 1023;
    const float* x1 = RES1 + (size_t)r*Dn;
    const float* gw = out_all + OFF_GROWTH + (size_t)(b*T1 + t + 1)*Dn;
    float vals[4]; float s = 0.f;
#pragma unroll
    for (int i = 0; i < 4; i++) {
        int d = threadIdx.x + i*128;
        vals[i] = x1[d] - gw[d];
        s += vals[i];
    }
    float mu = block_reduce_sum(s, red) * (1.0f/512.0f);
    float vs = 0.f;
#pragma unroll
    for (int i = 0; i < 4; i++) { float c = vals[i]-mu; vs += c*c; }
    float var = block_reduce_sum(vs, red) * (1.0f/512.0f);
    float inv = rsqrtf(var + 1e-5f);
#pragma unroll
    for (int i = 0; i < 4; i++) {
        int d = threadIdx.x + i*128;
        R2B[(size_t)r*Dn + d] = (vals[i]-mu)*inv*ng[d] + nb[d];
    }
}

__global__ __launch_bounds__(128) void res3_kernel(float* __restrict__ out_all,
                                                   const float* __restrict__ ng,
                                                   const float* __restrict__ nb) {
    __shared__ float red[32];
    int r = blockIdx.x;
    float vals[4]; float s = 0.f;
#pragma unroll
    for (int i = 0; i < 4; i++) {
        int d = threadIdx.x + i*128;
        vals[i] = R2B[(size_t)r*Dn + d] + FOUT[(size_t)r*Dn + d];
        s += vals[i];
    }
    float mu = block_reduce_sum(s, red) * (1.0f/512.0f);
    float vs = 0.f;
#pragma unroll
    for (int i = 0; i < 4; i++) { float c = vals[i]-mu; vs += c*c; }
    float var = block_reduce_sum(vs, red) * (1.0f/512.0f);
    float inv = rsqrtf(var + 1e-5f);
#pragma unroll
    for (int i = 0; i < 4; i++) {
        int d = threadIdx.x + i*128;
        out_all[OFF_RES3 + (size_t)r*Dn + d] = (vals[i]-mu)*inv*ng[d] + nb[d];
    }
}

// ---------------- level projections ----------------
__global__ __launch_bounds__(256) void levelproj_kernel(const float* __restrict__ out_all,
                                                        const float* __restrict__ gpw,
                                                        const float* __restrict__ spw) {
    int warp = (blockIdx.x*256 + threadIdx.x) >> 5;
    int lane = threadIdx.x & 31;
    if (warp >= Bn*Tn) return;
    int b = warp >> 10, t = warp & 1023;
    const float* gr = out_all + OFF_GROWTH + (size_t)(b*T1 + t)*Dn;
    const float* se = out_all + OFF_SEASON + (size_t)(b*TP + t)*Dn;
    float ag[7] = {}, as_[7] = {};
    for (int d = lane; d < 512; d += 32) {
        float g = gr[d], s = se[d];
#pragma unroll
        for (int c = 0; c < 7; c++) { ag[c] += g*gpw[d*7+c]; as_[c] += s*spw[d*7+c]; }
    }
#pragma unroll
    for (int c = 0; c < 7; c++) {
        for (int o = 16; o; o >>= 1) {
            ag[c]  += __shfl_xor_sync(0xffffffffu, ag[c],  o);
            as_[c] += __shfl_xor_sync(0xffffffffu, as_[c], o);
        }
    }
    if (lane == 0) {
#pragma unroll
        for (int c = 0; c < 7; c++) {
            GS_G[(size_t)warp*7 + c] = ag[c];
            GS_S[(size_t)warp*7 + c] = as_[c];
        }
    }
}

// ---------------- level EMA: blocked parallel scan ----------------
__global__ void level_passA(const float* __restrict__ level,
                            const float* __restrict__ lsw) {
    int gid = blockIdx.x*blockDim.x + threadIdx.x;   // 112*16 = 1792
    if (gid >= Bn*COUTn*GSEG) return;
    int ch = gid % (Bn*COUTn), seg = gid / (Bn*COUTn);
    int b = ch / COUTn, c = ch % COUTn;
    float w = 1.f/(1.f + expf(-lsw[c]));
    float omw = 1.f - w;
    int t0 = seg * GSEGLEN;
    const float* lp = level + (size_t)b*Tn*COUTn + c;
    const float* gp = GS_G  + (size_t)b*Tn*COUTn + c;
    const float* sp = GS_S  + (size_t)b*Tn*COUTn + c;
    float z = 0.f;
    for (int l = 0; l < GSEGLEN; l++) {
        int t = t0 + l;
        float u = omw*(lp[t*COUTn] - sp[t*COUTn]) + w*gp[t*COUTn];
        z = w*z + u;
    }
    LZ[(size_t)ch*GSEG + seg] = z;
}

__global__ void level_carry(const float* __restrict__ lsw,
                            const float* __restrict__ lv0) {
    int ch = threadIdx.x;
    if (ch >= Bn*COUTn) return;
    int c = ch % COUTn;
    float w = 1.f/(1.f + expf(-lsw[c]));
    float w64 = 1.f;
    { float p = w; int e = GSEGLEN; while (e) { if (e & 1) w64 *= p; p *= p; e >>= 1; } }
    float y = lv0[c];
#pragma unroll
    for (int seg = 0; seg < GSEG; seg++) {
        LCARRY[(size_t)ch*GSEG + seg] = y;
        y = w64*y + LZ[(size_t)ch*GSEG + seg];
    }
}

__global__ void level_passB(const float* __restrict__ level,
                            const float* __restrict__ lsw,
                            float* __restrict__ out_all) {
    int gid = blockIdx.x*blockDim.x + threadIdx.x;
    if (gid >= Bn*COUTn*GSEG) return;
    int ch = gid % (Bn*COUTn), seg = gid / (Bn*COUTn);
    int b = ch / COUTn, c = ch % COUTn;
    float w = 1.f/(1.f + expf(-lsw[c]));
    float omw = 1.f - w;
    int t0 = seg * GSEGLEN;
    const float* lp = level + (size_t)b*Tn*COUTn + c;
    const float* gp = GS_G  + (size_t)b*Tn*COUTn + c;
    const float* sp = GS_S  + (size_t)b*Tn*COUTn + c;
    float* op = out_all + OFF_LEVEL + (size_t)b*Tn*COUTn + c;
    float y = LCARRY[(size_t)ch*GSEG + seg];
    for (int l = 0; l < GSEGLEN; l++) {
        int t = t0 + l;
        float u = omw*(lp[t*COUTn] - sp[t*COUTn]) + w*gp[t*COUTn];
        y = w*y + u;
        op[t*COUTn] = y;
    }
}

// ---------------- launch ----------------
extern "C" void kernel_launch(void* const* d_in, const int* in_sizes, int n_in,
                              void* d_out, int out_size) {
    const float* res      = (const float*)d_in[0];
    const float* level    = (const float*)d_in[1];
    const float* in_w     = (const float*)d_in[2];
    const float* out_w    = (const float*)d_in[3];
    const float* z0       = (const float*)d_in[4];
    const float* gsw      = (const float*)d_in[5];
    const float* gv0      = (const float*)d_in[6];
    const float* ff_w1    = (const float*)d_in[7];
    const float* ff_w2    = (const float*)d_in[8];
    const float* n1g      = (const float*)d_in[9];
    const float* n1b      = (const float*)d_in[10];
    const float* n2g      = (const float*)d_in[11];
    const float* n2b      = (const float*)d_in[12];
    const float* gpw      = (const float*)d_in[13];
    const float* spw      = (const float*)d_in[14];
    const float* lsw      = (const float*)d_in[15];
    const float* lv0      = (const float*)d_in[16];
    float* out = (float*)d_out;

    float *pRES1, *pVBUF, *pGBUF, *pR2, *pFBUF, *pFOUT;
    cudaGetSymbolAddress((void**)&pRES1, RES1);
    cudaGetSymbolAddress((void**)&pVBUF, VBUF);
    cudaGetSymbolAddress((void**)&pGBUF, GBUF);
    cudaGetSymbolAddress((void**)&pR2,   R2B);
    cudaGetSymbolAddress((void**)&pFBUF, FBUF);
    cudaGetSymbolAddress((void**)&pFOUT, FOUT);

    // 1) FFT + top-k
    fft_topk_kernel<<<Bn*(Dn/4), 256>>>(res);
    // 2) season + res1
    season_kernel<<<dim3(2, Bn, 10), 256>>>(res, out);
    // 3) v = res1 @ in_proj_w
    tf32gemm_kernel<<<dim3(Dn/128, (Bn*Tn)/128), 256>>>(pRES1, in_w, pVBUF,
                                                        Bn*Tn, Dn, Dn, 0);
    // 4) diffs + EMA (blocked scan) -> GBUF [B,T+1,512]
    growth_passA<<<(Bn*Dn*GSEG)/256, 256>>>(gsw, z0);
    growth_carry<<<(Bn*Dn)/256, 256>>>(gsw, gv0);
    growth_passB<<<(Bn*Dn*GSEG)/256, 256>>>(gsw, z0, gv0);
    // 5) growth = GBUF @ out_proj_w -> d_out
    tf32gemm_kernel<<<dim3(Dn/128, (Bn*T1 + 127)/128), 256>>>(pGBUF, out_w,
                                                              out + OFF_GROWTH,
                                                              Bn*T1, Dn, Dn, 0);
    // 6) res2 = LN(res1 - growth[:,1:])
    res2_kernel<<<Bn*Tn, 128>>>(out, n1g, n1b);
    // 7) ffn1 = gelu(res2 @ ff_w1)
    tf32gemm_kernel<<<dim3(LATENTn/128, (Bn*Tn)/128), 256>>>(pR2, ff_w1, pFBUF,
                                                             Bn*Tn, LATENTn, Dn, 1);
    // 8) ffn2 = ffn1 @ ff_w2
    tf32gemm_kernel<<<dim3(Dn/128, (Bn*Tn)/128), 256>>>(pFBUF, ff_w2, pFOUT,
                                                        Bn*Tn, Dn, LATENTn, 0);
    // 9) res3 = LN(res2 + ffn2) -> d_out
    res3_kernel<<<Bn*Tn, 128>>>(out, n2g, n2b);
    // 10) level projections
    levelproj_kernel<<<(Bn*Tn*32)/256, 256>>>(out, gpw, spw);
    // 11) level EMA (blocked scan) -> d_out
    level_passA<<<(Bn*COUTn*GSEG + 255)/256, 256>>>(level, lsw);
    level_carry<<<1, 128>>>(lsw, lv0);
    level_passB<<<(Bn*COUTn*GSEG + 255)/256, 256>>>(level, lsw, out);
}